// round 6
// baseline (speedup 1.0000x reference)
#include <cuda_runtime.h>
#include <stdint.h>

// ---------------- problem constants ----------------
#define BATCH 128
#define TSTEPS 300
#define CLIP 50
#define DIN 2312
#define DINP 2320          // K padded to multiple of 16
#define HID 800
#define HIDP 896
#define NC 10
#define MROWS (BATCH*CLIP) // 6400
#define NCH (DINP/16)      // 145 k-chunks of 16

// ---------------- scratch ----------------
__device__ float g_Xc[(size_t)MROWS * DINP];   // A  [6400][2320]
__device__ float g_Bt[(size_t)DINP * HIDP];    // B^T [2320][896]  (k-major)
__device__ float g_V1[(size_t)MROWS * HIDP];   // V1 [6400][896]

// ---------------- PTX helpers ----------------
typedef unsigned long long ull;
__device__ __forceinline__ uint32_t smem_u32(const void* p) {
    uint32_t a;
    asm("{ .reg .u64 t; cvta.to.shared.u64 t, %1; cvt.u32.u64 %0, t; }" : "=r"(a) : "l"(p));
    return a;
}
__device__ __forceinline__ void cp_async16(uint32_t dst, const void* src) {
    asm volatile("cp.async.cg.shared.global [%0], [%1], 16;" :: "r"(dst), "l"(src));
}
#define CP_COMMIT() asm volatile("cp.async.commit_group;" ::: "memory")
__device__ __forceinline__ void ffma2(ull& d, ull a, ull b) {
    asm("fma.rn.f32x2 %0, %1, %2, %0;" : "+l"(d) : "l"(a), "l"(b));
}
__device__ __forceinline__ ull pack2(float x) {
    ull r; asm("mov.b64 %0, {%1, %1};" : "=l"(r) : "f"(x)); return r;
}

// ---------------- kernel 1: paste X into output ----------------
__global__ void paste_kernel(const float* __restrict__ inp,
                             const int* __restrict__ idx,
                             float* __restrict__ outX) {
    long tid = (long)blockIdx.x * blockDim.x + threadIdx.x;
    const long total = (long)BATCH * DIN * (TSTEPS / 4);
    if (tid >= total) return;
    int  c4  = (int)(tid % (TSTEPS / 4));
    long row = tid / (TSTEPS / 4);
    int  i   = (int)(row / DIN);
    int  d   = (int)(row % DIN);
    int  t0  = c4 * 4;
    int  id  = idx[i];
    float4 v;
    float* vv = (float*)&v;
    const float* src = inp + (long)i * DIN * CLIP + (long)d * CLIP;
#pragma unroll
    for (int u = 0; u < 4; u++) {
        int s = t0 + u - id;
        vv[u] = (s >= 0 && s < CLIP) ? src[s] : 0.f;
    }
    *(float4*)&outX[row * TSTEPS + t0] = v;
}

// ---------------- kernel 2: transpose clips into Xc [6400][2320] ----------------
__global__ void transpose_kernel(const float* __restrict__ inp) {
    __shared__ float tile[32][51];
    int i  = blockIdx.x;
    int d0 = blockIdx.y * 32;
    int tid = threadIdx.x;  // 256
    for (int p = tid; p < 32 * CLIP; p += 256) {
        int dd = p / CLIP, s = p % CLIP;
        int d = d0 + dd;
        tile[dd][s] = (d < DIN) ? inp[(long)i * DIN * CLIP + (long)d * CLIP + s] : 0.f;
    }
    __syncthreads();
    for (int p = tid; p < CLIP * 32; p += 256) {
        int s = p / 32, dd = p % 32;
        int d = d0 + dd;
        if (d < DINP)
            g_Xc[((long)i * CLIP + s) * DINP + d] = tile[dd][s];
    }
}

// ---------------- kernel 3: W1 -> Bt [2320][896] (k-major, padded) ----------------
__global__ void convBt_kernel(const float* __restrict__ W1) {
    int d = blockIdx.x;          // 0..2319
    int t = threadIdx.x;         // 224 threads -> 896 floats
    float4 v;
    float* vv = (float*)&v;
#pragma unroll
    for (int u = 0; u < 4; u++) {
        int n = t * 4 + u;
        vv[u] = (d < DIN && n < HID) ? W1[(long)n * DIN + d] : 0.f;
    }
    *(float4*)&g_Bt[(long)d * HIDP + t * 4] = v;
}

// ---------------- kernel 4: fp32x2 FFMA GEMM v2 (bit-identical k-order) ----------
// BM=64, BN=128, BK=16, 3-stage cp.async, conflict-free B smem reads.
#define BM 64
#define BN 128
#define BK 16
#define NST 3
#define A_STG 4096                 // 64*16*4
#define B_STG 8192                 // 16*128*4
#define STG (A_STG + B_STG)        // 12288
#define GEMM_SMEM (NST * STG)      // 36864

__global__ __launch_bounds__(256, 2) void gemm_kernel() {
    extern __shared__ char dsm[];
    uint32_t sb = smem_u32(dsm);
    int tid = threadIdx.x;
    int m0 = blockIdx.x * BM;
    int n0 = blockIdx.y * BN;
    int tx = tid & 15;         // 16 over N
    int ty = tid >> 4;         // 16 over M
    int ty4 = ty * 4;
    int tx2 = tx * 2;

    // load-index precompute
    int amr = tid >> 2, ak = (tid & 3) * 4;           // A: m row 0..63, k off {0,4,8,12}
    const float* Ag = g_Xc + (long)(m0 + amr) * DINP + ak;
    uint32_t aDst = (uint32_t)(amr * 64 + ak * 4);    // m*64B + k*4B... (k off *16B/4) = ak*4? careful below

    ull acc[4][4];
#pragma unroll
    for (int r = 0; r < 4; r++)
#pragma unroll
        for (int q = 0; q < 4; q++) acc[r][q] = 0ull;

    // prologue: chunks 0..NST-2
#pragma unroll
    for (int c = 0; c < NST - 1; ++c) {
        uint32_t st = sb + c * STG;
        long k0 = (long)c * BK;
        cp_async16(st + amr * 64 + (tid & 3) * 16, Ag + k0);
#pragma unroll
        for (int j = 0; j < 2; ++j) {
            int id = tid + 256 * j;
            int kk = id >> 5, n16 = id & 31;
            cp_async16(st + A_STG + kk * 512 + n16 * 16,
                       g_Bt + (long)(k0 + kk) * HIDP + n0 + n16 * 4);
        }
        CP_COMMIT();
    }

    for (int c = 0; c < NCH; ++c) {
        int cl = c + NST - 1;
        if (cl < NCH) {
            uint32_t st = sb + (cl % NST) * STG;
            long k0 = (long)cl * BK;
            cp_async16(st + amr * 64 + (tid & 3) * 16, Ag + k0);
#pragma unroll
            for (int j = 0; j < 2; ++j) {
                int id = tid + 256 * j;
                int kk = id >> 5, n16 = id & 31;
                cp_async16(st + A_STG + kk * 512 + n16 * 16,
                           g_Bt + (long)(k0 + kk) * HIDP + n0 + n16 * 4);
            }
        }
        CP_COMMIT();
        asm volatile("cp.async.wait_group %0;" :: "n"(NST - 1) : "memory");
        __syncthreads();

        const char* aT = dsm + (c % NST) * STG;
        const char* bT = aT + A_STG;
#pragma unroll
        for (int kk = 0; kk < BK; ++kk) {
            ull ap[4];
#pragma unroll
            for (int r = 0; r < 4; r++)
                ap[r] = pack2(*(const float*)(aT + ((ty4 + r) * BK + kk) * 4));
            ull bq[4];
#pragma unroll
            for (int q = 0; q < 4; q++)
                bq[q] = *(const ull*)(bT + (kk * BN + tx2 + 32 * q) * 4);
#pragma unroll
            for (int r = 0; r < 4; r++)
#pragma unroll
                for (int q = 0; q < 4; q++)
                    ffma2(acc[r][q], ap[r], bq[q]);
        }
        __syncthreads();
    }

    // epilogue: float2 stores, coalesced across tx
#pragma unroll
    for (int r = 0; r < 4; r++) {
        long m = m0 + ty4 + r;
#pragma unroll
        for (int q = 0; q < 4; q++) {
            long n = n0 + tx2 + 32 * q;
            *(float2*)&g_V1[m * HIDP + n] = *(float2*)&acc[r][q];
        }
    }
}

// ---------------- kernel 5: sequential scan (1 CTA per batch row) ----------------
__global__ __launch_bounds__(256, 1) void scan_kernel(
    const int*   __restrict__ idx,
    const float* __restrict__ b1,
    const float* __restrict__ W2,   // [10][800]
    const float* __restrict__ b2,   // [10]
    const float* __restrict__ Wc,   // [804]
    const float* __restrict__ bc,   // [1]
    float*       __restrict__ out)  // rate at out[0..1280)
{
    __shared__ float W2t[HID][NC];
    __shared__ float Wcs[HID];
    __shared__ float b1s[HID];
    __shared__ float wpart[8][11];
    __shared__ float cs_sh;
    __shared__ float bgt_sh;

    int i   = blockIdx.x;
    int tid = threadIdx.x;

    for (int p = tid; p < HID * NC; p += 256) {
        int k = p / HID, j = p % HID;
        W2t[j][k] = W2[p];
    }
    for (int p = tid; p < HID; p += 256) { Wcs[p] = Wc[p]; b1s[p] = b1[p]; }
    if (tid == 0) cs_sh = 0.f;

    float h1m[4] = {0.f, 0.f, 0.f, 0.f};
    float h1s[4] = {0.f, 0.f, 0.f, 0.f};
    int  jj[4]; bool jv[4];
#pragma unroll
    for (int r = 0; r < 4; r++) { jj[r] = tid + 256 * r; jv[r] = (jj[r] < HID); }

    float h2m = 0.f, h2s = 0.f, sum2 = 0.f, my_b2 = 0.f;
    float cm = 0.f, bgt = 1.f;
    float wc0 = 0.f, wc1 = 0.f, wc2 = 0.f, wc3 = 0.f, bc0 = 0.f;
    if (tid < 10) my_b2 = b2[tid];
    if (tid == 10) {
        wc0 = Wc[800]; wc1 = Wc[801]; wc2 = Wc[802]; wc3 = Wc[803];
        bc0 = bc[0];
    }
    int myidx = idx[i];
    __syncthreads();

    for (int t = 0; t < TSTEPS; t++) {
        float g = (t == 0) ? 1.f : cs_sh;
        int s = t - myidx;
        bool act = (s >= 0) && (s < CLIP) && (g != 0.f);
        int srow = act ? s : 0;
        const float* v1 = &g_V1[((long)i * CLIP + srow) * HIDP];

        float part[11];
#pragma unroll
        for (int k = 0; k < 11; k++) part[k] = 0.f;

#pragma unroll
        for (int r = 0; r < 4; r++) {
            if (jv[r]) {
                float v = act ? g * v1[jj[r]] : 0.f;
                float m = h1m[r] * 0.1f * (1.f - h1s[r]) + v + b1s[jj[r]];
                h1m[r] = m;
                float sp = (m > 0.5f) ? 1.f : 0.f;
                h1s[r] = sp;
                if (sp != 0.f) {
#pragma unroll
                    for (int k = 0; k < 10; k++) part[k] += W2t[jj[r]][k];
                    part[10] += Wcs[jj[r]];
                }
            }
        }
#pragma unroll
        for (int k = 0; k < 11; k++) {
#pragma unroll
            for (int off = 16; off; off >>= 1)
                part[k] += __shfl_down_sync(0xffffffffu, part[k], off);
        }
        if ((tid & 31) == 0) {
#pragma unroll
            for (int k = 0; k < 11; k++) wpart[tid >> 5][k] = part[k];
        }
        __syncthreads();

        if (tid < 10) {
            float red = 0.f;
#pragma unroll
            for (int w = 0; w < 8; w++) red += wpart[w][tid];
            float m = h2m * 0.1f * (1.f - h2s) + red + my_b2;
            h2m = m;
            h2s = (m > 0.5f) ? 1.f : 0.f;
            sum2 += h2s;
        } else if (tid == 10) {
            float red = 0.f;
#pragma unroll
            for (int w = 0; w < 8; w++) red += wpart[w][10];
            float csprev = cs_sh;
            if (csprev == 1.f) bgt += 1.f;
            float fq = wc0
                     + (((t % 2)   == 0) ? wc1 : 0.f)
                     + (((t % 10)  == 0) ? wc2 : 0.f)
                     + (((t % 100) == 0) ? wc3 : 0.f);
            cm = cm * 0.1f * (1.f - csprev) + red + fq + bc0;
            cs_sh = (cm > 0.5f) ? 1.f : 0.f;
        }
        __syncthreads();
    }

    if (tid == 10) bgt_sh = bgt;
    __syncthreads();
    if (tid < 10) out[i * NC + tid] = sum2 / bgt_sh;
}

// ---------------- launcher ----------------
extern "C" void kernel_launch(void* const* d_in, const int* in_sizes, int n_in,
                              void* d_out, int out_size) {
    const float* inp = (const float*)d_in[0];
    const int*   idx = (const int*)d_in[2];
    const float* W1  = (const float*)d_in[3];
    const float* b1  = (const float*)d_in[4];
    const float* W2  = (const float*)d_in[5];
    const float* b2  = (const float*)d_in[6];
    const float* Wc  = (const float*)d_in[7];
    const float* bc  = (const float*)d_in[8];
    float* out = (float*)d_out;

    cudaFuncSetAttribute(gemm_kernel, cudaFuncAttributeMaxDynamicSharedMemorySize,
                         GEMM_SMEM);

    {
        long total = (long)BATCH * DIN * (TSTEPS / 4);
        paste_kernel<<<(int)((total + 255) / 256), 256>>>(inp, idx, out + BATCH * NC);
    }
    {
        dim3 grid(BATCH, (DINP + 31) / 32);
        transpose_kernel<<<grid, 256>>>(inp);
    }
    convBt_kernel<<<DINP, 224>>>(W1);
    {
        dim3 grid(MROWS / BM, HIDP / BN);
        gemm_kernel<<<grid, 256, GEMM_SMEM>>>();
    }
    scan_kernel<<<BATCH, 256>>>(idx, b1, W2, b2, Wc, bc, out);
}

// round 8
// speedup vs baseline: 1.6649x; 1.6649x over previous
#include <cuda_runtime.h>
#include <stdint.h>

// ---------------- problem constants ----------------
#define BATCH 128
#define TSTEPS 300
#define CLIP 50
#define DIN 2312
#define DINP 2320          // K padded to multiple of 16 (zero-padded; FFMA +0 is exact)
#define HID 800
#define HIDP 896
#define NC 10
#define MROWS (BATCH*CLIP) // 6400
#define NCH (DINP/16)      // 145 k-chunks of 16

// ---------------- scratch ----------------
__device__ float g_XcT[(size_t)DINP * MROWS];  // A^T [2320][6400] (k-major over m)
__device__ float g_Bt[(size_t)DINP * HIDP];    // B^T [2320][896]  (k-major over n)
__device__ float g_V1[(size_t)MROWS * HIDP];   // V1 [6400][896]

// ---------------- PTX helpers ----------------
typedef unsigned long long ull;
__device__ __forceinline__ uint32_t smem_u32(const void* p) {
    uint32_t a;
    asm("{ .reg .u64 t; cvta.to.shared.u64 t, %1; cvt.u32.u64 %0, t; }" : "=r"(a) : "l"(p));
    return a;
}
__device__ __forceinline__ void cp_async16(uint32_t dst, const void* src) {
    asm volatile("cp.async.cg.shared.global [%0], [%1], 16;" :: "r"(dst), "l"(src));
}
#define CP_COMMIT() asm volatile("cp.async.commit_group;" ::: "memory")
__device__ __forceinline__ void ffma2(ull& d, ull a, ull b) {
    asm("fma.rn.f32x2 %0, %1, %2, %0;" : "+l"(d) : "l"(a), "l"(b));
}
__device__ __forceinline__ ull pack2(float x) {
    ull r; asm("mov.b64 %0, {%1, %1};" : "=l"(r) : "f"(x)); return r;
}

// ---------------- kernel 1: paste X into output ----------------
__global__ void paste_kernel(const float* __restrict__ inp,
                             const int* __restrict__ idx,
                             float* __restrict__ outX) {
    long tid = (long)blockIdx.x * blockDim.x + threadIdx.x;
    const long total = (long)BATCH * DIN * (TSTEPS / 4);
    if (tid >= total) return;
    int  c4  = (int)(tid % (TSTEPS / 4));
    long row = tid / (TSTEPS / 4);
    int  i   = (int)(row / DIN);
    int  d   = (int)(row % DIN);
    int  t0  = c4 * 4;
    int  id  = idx[i];
    float4 v;
    float* vv = (float*)&v;
    const float* src = inp + (long)i * DIN * CLIP + (long)d * CLIP;
#pragma unroll
    for (int u = 0; u < 4; u++) {
        int s = t0 + u - id;
        vv[u] = (s >= 0 && s < CLIP) ? src[s] : 0.f;
    }
    *(float4*)&outX[row * TSTEPS + t0] = v;
}

// ---------------- kernel 2: clips -> XcT [2320][6400] (k-major) ----------------
__global__ void transposeA_kernel(const float* __restrict__ inp) {
    __shared__ float tile[32][51];
    int i  = blockIdx.x;
    int d0 = blockIdx.y * 32;
    int tid = threadIdx.x;  // 256
    for (int p = tid; p < 32 * CLIP; p += 256) {
        int dd = p / CLIP, s = p % CLIP;
        int d = d0 + dd;
        tile[dd][s] = (d < DIN) ? inp[((long)i * DIN + d) * CLIP + s] : 0.f;
    }
    __syncthreads();
    // coalesced writes: s fast within each d-row (200B runs)
    for (int p = tid; p < 32 * CLIP; p += 256) {
        int dd = p / CLIP, s = p % CLIP;
        int d = d0 + dd;
        if (d < DINP)
            g_XcT[(long)d * MROWS + i * CLIP + s] = tile[dd][s];
    }
}

// ---------------- kernel 3: W1 -> Bt [2320][896] via coalesced smem transpose ----
__global__ void transposeB_kernel(const float* __restrict__ W1) {
    __shared__ float tile[32][33];
    int k0 = blockIdx.x * 32;
    int n0 = blockIdx.y * 32;
    int tx = threadIdx.x & 31;     // along k on load, along n on store
    int ty = threadIdx.x >> 5;     // 0..7
#pragma unroll
    for (int r = 0; r < 4; r++) {
        int n = n0 + ty + r * 8;
        int k = k0 + tx;
        tile[ty + r * 8][tx] = (n < HID && k < DIN) ? W1[(long)n * DIN + k] : 0.f;
    }
    __syncthreads();
#pragma unroll
    for (int r = 0; r < 4; r++) {
        int k = k0 + ty + r * 8;
        int n = n0 + tx;
        if (k < DINP && n < HIDP)
            g_Bt[(long)k * HIDP + n] = tile[tx][ty + r * 8];
    }
}

// ---------------- kernel 4: fp32x2 FFMA GEMM v3 (bit-identical k-order) --------
// BM=128, BN=128, BK=16, 3-stage cp.async. A smem m-major (broadcast LDS.128),
// B smem n-major (conflict-free LDS.64). Per-element ascending-k FFMA2 chain.
#define BK 16
#define NST 3
#define A_STG 8192                 // 16*128*4
#define B_STG 8192
#define STG (A_STG + B_STG)        // 16384
#define GEMM_SMEM (NST * STG)      // 49152

__global__ __launch_bounds__(256, 2) void gemm_kernel() {
    extern __shared__ char dsm[];
    uint32_t sb = smem_u32(dsm);
    int tid = threadIdx.x;
    int m0 = blockIdx.x * 128;
    int n0 = blockIdx.y * 128;
    int tx = tid & 15;         // 16 over N
    int ty = tid >> 4;         // 16 over M (8 rows each)

    // loader indices: id in [0,512): row kk = id>>5, col4 = (id&31)*4
    int lkk = tid >> 5;            // 0..7  (+8 with j)
    int lc4 = (tid & 31) * 4;

    ull acc[8][4];
#pragma unroll
    for (int r = 0; r < 8; r++)
#pragma unroll
        for (int q = 0; q < 4; q++) acc[r][q] = 0ull;

    // prologue: chunks 0..NST-2
#pragma unroll
    for (int c = 0; c < NST - 1; ++c) {
        uint32_t st = sb + c * STG;
        long k0 = (long)c * BK;
#pragma unroll
        for (int j = 0; j < 2; ++j) {
            int kk = lkk + j * 8;
            cp_async16(st + kk * 512 + lc4 * 4,
                       g_XcT + (k0 + kk) * MROWS + m0 + lc4);
            cp_async16(st + A_STG + kk * 512 + lc4 * 4,
                       g_Bt + (k0 + kk) * HIDP + n0 + lc4);
        }
        CP_COMMIT();
    }

    for (int c = 0; c < NCH; ++c) {
        int cl = c + NST - 1;
        if (cl < NCH) {
            uint32_t st = sb + (cl % NST) * STG;
            long k0 = (long)cl * BK;
#pragma unroll
            for (int j = 0; j < 2; ++j) {
                int kk = lkk + j * 8;
                cp_async16(st + kk * 512 + lc4 * 4,
                           g_XcT + (k0 + kk) * MROWS + m0 + lc4);
                cp_async16(st + A_STG + kk * 512 + lc4 * 4,
                           g_Bt + (k0 + kk) * HIDP + n0 + lc4);
            }
        }
        CP_COMMIT();
        asm volatile("cp.async.wait_group %0;" :: "n"(NST - 1) : "memory");
        __syncthreads();

        const char* aT = dsm + (c % NST) * STG;
        const char* bT = aT + A_STG;
#pragma unroll
        for (int kk = 0; kk < BK; ++kk) {
            float4 a0 = *(const float4*)(aT + kk * 512 + ty * 32);
            float4 a1 = *(const float4*)(aT + kk * 512 + ty * 32 + 16);
            const ull* bp = (const ull*)(bT + kk * 512);
            ull bq[4];
            bq[0] = bp[tx * 2];
            bq[1] = bp[tx * 2 + 1];
            bq[2] = bp[32 + tx * 2];
            bq[3] = bp[33 + tx * 2];
            ull ar[8];
            ar[0] = pack2(a0.x); ar[1] = pack2(a0.y);
            ar[2] = pack2(a0.z); ar[3] = pack2(a0.w);
            ar[4] = pack2(a1.x); ar[5] = pack2(a1.y);
            ar[6] = pack2(a1.z); ar[7] = pack2(a1.w);
#pragma unroll
            for (int r = 0; r < 8; r++)
#pragma unroll
                for (int q = 0; q < 4; q++)
                    ffma2(acc[r][q], ar[r], bq[q]);
        }
        __syncthreads();
    }

    // epilogue: element n-cols: q0,q1 -> n0+tx*4..+3 ; q2,q3 -> n0+64+tx*4..+3
#pragma unroll
    for (int r = 0; r < 8; r++) {
        long m = m0 + ty * 8 + r;
        float2 f0 = *(float2*)&acc[r][0];
        float2 f1 = *(float2*)&acc[r][1];
        float2 f2 = *(float2*)&acc[r][2];
        float2 f3 = *(float2*)&acc[r][3];
        *(float4*)&g_V1[m * HIDP + n0 + tx * 4]      = make_float4(f0.x, f0.y, f1.x, f1.y);
        *(float4*)&g_V1[m * HIDP + n0 + 64 + tx * 4] = make_float4(f2.x, f2.y, f3.x, f3.y);
    }
}

// ---------------- kernel 5: sequential scan with V1 prefetch ----------------
__global__ __launch_bounds__(256, 1) void scan_kernel(
    const int*   __restrict__ idx,
    const float* __restrict__ b1,
    const float* __restrict__ W2,
    const float* __restrict__ b2,
    const float* __restrict__ Wc,
    const float* __restrict__ bc,
    float*       __restrict__ out)
{
    __shared__ float W2t[HID][NC];
    __shared__ float Wcs[HID];
    __shared__ float b1s[HID];
    __shared__ float wpart[8][11];
    __shared__ float cs_sh;
    __shared__ float bgt_sh;

    int i   = blockIdx.x;
    int tid = threadIdx.x;

    for (int p = tid; p < HID * NC; p += 256) {
        int k = p / HID, j = p % HID;
        W2t[j][k] = W2[p];
    }
    for (int p = tid; p < HID; p += 256) { Wcs[p] = Wc[p]; b1s[p] = b1[p]; }
    if (tid == 0) cs_sh = 0.f;

    float h1m[4] = {0.f, 0.f, 0.f, 0.f};
    float h1s[4] = {0.f, 0.f, 0.f, 0.f};
    int  jj[4]; bool jv[4];
#pragma unroll
    for (int r = 0; r < 4; r++) { jj[r] = tid + 256 * r; jv[r] = (jj[r] < HID); }

    float h2m = 0.f, h2s = 0.f, sum2 = 0.f, my_b2 = 0.f;
    float cm = 0.f, bgt = 1.f;
    float wc0 = 0.f, wc1 = 0.f, wc2 = 0.f, wc3 = 0.f, bc0 = 0.f;
    if (tid < 10) my_b2 = b2[tid];
    if (tid == 10) {
        wc0 = Wc[800]; wc1 = Wc[801]; wc2 = Wc[802]; wc3 = Wc[803];
        bc0 = bc[0];
    }
    int myidx = idx[i];
    const float* v1base = &g_V1[(long)i * CLIP * HIDP];
    __syncthreads();

    // prefetch row for t = 0
    float vp[4] = {0.f, 0.f, 0.f, 0.f};
    {
        int s0 = 0 - myidx;
        if (s0 >= 0 && s0 < CLIP) {
            const float* v1 = v1base + (long)s0 * HIDP;
#pragma unroll
            for (int r = 0; r < 4; r++) if (jv[r]) vp[r] = v1[jj[r]];
        }
    }

    for (int t = 0; t < TSTEPS; t++) {
        float g = (t == 0) ? 1.f : cs_sh;
        int s = t - myidx;
        bool act = (s >= 0) && (s < CLIP) && (g != 0.f);

        float part[11];
#pragma unroll
        for (int k = 0; k < 11; k++) part[k] = 0.f;

#pragma unroll
        for (int r = 0; r < 4; r++) {
            if (jv[r]) {
                float v = act ? vp[r] : 0.f;   // gate is exactly 1 when act
                float m = h1m[r] * 0.1f * (1.f - h1s[r]) + v + b1s[jj[r]];
                h1m[r] = m;
                float sp = (m > 0.5f) ? 1.f : 0.f;
                h1s[r] = sp;
                if (sp != 0.f) {
#pragma unroll
                    for (int k = 0; k < 10; k++) part[k] += W2t[jj[r]][k];
                    part[10] += Wcs[jj[r]];
                }
            }
        }

        // prefetch row for t+1 (gate-independent), overlaps reductions+barriers
        float vn[4] = {0.f, 0.f, 0.f, 0.f};
        int sn = t + 1 - myidx;
        if (t + 1 < TSTEPS && sn >= 0 && sn < CLIP) {
            const float* v1n = v1base + (long)sn * HIDP;
#pragma unroll
            for (int r = 0; r < 4; r++) if (jv[r]) vn[r] = __ldg(&v1n[jj[r]]);
        }

#pragma unroll
        for (int k = 0; k < 11; k++) {
#pragma unroll
            for (int off = 16; off; off >>= 1)
                part[k] += __shfl_down_sync(0xffffffffu, part[k], off);
        }
        if ((tid & 31) == 0) {
#pragma unroll
            for (int k = 0; k < 11; k++) wpart[tid >> 5][k] = part[k];
        }
        __syncthreads();

        if (tid < 10) {
            float red = 0.f;
#pragma unroll
            for (int w = 0; w < 8; w++) red += wpart[w][tid];
            float m = h2m * 0.1f * (1.f - h2s) + red + my_b2;
            h2m = m;
            h2s = (m > 0.5f) ? 1.f : 0.f;
            sum2 += h2s;
        } else if (tid == 10) {
            float red = 0.f;
#pragma unroll
            for (int w = 0; w < 8; w++) red += wpart[w][10];
            float csprev = cs_sh;
            if (csprev == 1.f) bgt += 1.f;
            float fq = wc0
                     + (((t % 2)   == 0) ? wc1 : 0.f)
                     + (((t % 10)  == 0) ? wc2 : 0.f)
                     + (((t % 100) == 0) ? wc3 : 0.f);
            cm = cm * 0.1f * (1.f - csprev) + red + fq + bc0;
            cs_sh = (cm > 0.5f) ? 1.f : 0.f;
        }
        __syncthreads();

#pragma unroll
        for (int r = 0; r < 4; r++) vp[r] = vn[r];
    }

    if (tid == 10) bgt_sh = bgt;
    __syncthreads();
    if (tid < 10) out[i * NC + tid] = sum2 / bgt_sh;
}

// ---------------- launcher ----------------
extern "C" void kernel_launch(void* const* d_in, const int* in_sizes, int n_in,
                              void* d_out, int out_size) {
    const float* inp = (const float*)d_in[0];
    const int*   idx = (const int*)d_in[2];
    const float* W1  = (const float*)d_in[3];
    const float* b1  = (const float*)d_in[4];
    const float* W2  = (const float*)d_in[5];
    const float* b2  = (const float*)d_in[6];
    const float* Wc  = (const float*)d_in[7];
    const float* bc  = (const float*)d_in[8];
    float* out = (float*)d_out;

    cudaFuncSetAttribute(gemm_kernel, cudaFuncAttributeMaxDynamicSharedMemorySize,
                         GEMM_SMEM);

    {
        long total = (long)BATCH * DIN * (TSTEPS / 4);
        paste_kernel<<<(int)((total + 255) / 256), 256>>>(inp, idx, out + BATCH * NC);
    }
    {
        dim3 grid(BATCH, (DINP + 31) / 32);
        transposeA_kernel<<<grid, 256>>>(inp);
    }
    {
        dim3 grid((DINP + 31) / 32, (HIDP + 31) / 32);
        transposeB_kernel<<<grid, 256>>>(W1);
    }
    {
        dim3 grid(MROWS / 128, HIDP / 128);
        gemm_kernel<<<grid, 256, GEMM_SMEM>>>();
    }
    scan_kernel<<<BATCH, 256>>>(idx, b1, W2, b2, Wc, bc, out);
}